// round 8
// baseline (speedup 1.0000x reference)
#include <cuda_runtime.h>
#include <cuda_fp16.h>
#include <math.h>
#include <stdint.h>

// ---------------- problem constants ----------------
#define N0   4096
#define EDG  131072
#define K1   3277      // ceil(0.8*4096)
#define K2   2622      // ceil(0.8*3277)
#define K3   2098      // ceil(0.8*2622)
#define KP1  3328      // K1 padded to 128 (GEMM N tiles)
#define KP2  2688
#define KP3  2176
#define KPM1 3328      // padded to 256 (GEMM M tiles)
#define KPM2 2816
#define KPM3 2304
#define KD1  4096      // GEMM K dim padded to 64
#define KD2  3328
#define KD3  2624
#define CH   64
#define DSPLIT 32
#define RSPLIT 16

// ---------------- device scratch (no allocation allowed) ----------------
__device__ float g_A0[(size_t)N0*N0];
__device__ float g_A1[(size_t)K1*K1];
__device__ float g_A2[(size_t)K2*K2];
__device__ float g_A3[(size_t)K3*K3];
__device__ __half g_Ah[(size_t)KPM1*KD1];  // GEMM operand A, [M,K] row-major
__device__ __half g_Bh[(size_t)KP1*KD1];   // GEMM operand B, [N,K] row-major
__device__ float g_x0[N0*CH];
__device__ float g_x1[K1*CH];
__device__ float g_x2[K2*CH];
__device__ float g_x3[K3*CH];
__device__ float g_xp[N0*CH];
__device__ float g_y [N0*CH];
__device__ float g_z [N0*CH];
__device__ float g_part [(size_t)RSPLIT*N0*CH];
__device__ float g_dpart[(size_t)DSPLIT*N0];
__device__ float g_dis[N0];
__device__ float g_slw[N0];
__device__ float g_score[N0];
__device__ float g_sval[N0];
__device__ int   g_perm0[K1];
__device__ int   g_perm1[K2];
__device__ int   g_perm2[K3];
__device__ int   g_rnk[N0];

static inline int cdiv(int a, int b) { return (a + b - 1) / b; }

// ---------------- elementwise ----------------
__global__ void k_zero(float* p, int n) {
    int i = blockIdx.x * blockDim.x + threadIdx.x;
    if (i < n) p[i] = 0.f;
}

__global__ void k_edges(const int* __restrict__ src, const int* __restrict__ dst,
                        float* __restrict__ A) {
    int i = blockIdx.x * blockDim.x + threadIdx.x;
    if (i >= EDG) return;
    int s = src[i], d = dst[i];
    if (s != d) atomicAdd(&A[(size_t)s * N0 + d], 1.0f);   // exact integer adds
}

__global__ void k_diag1(float* A) {
    int i = blockIdx.x * blockDim.x + threadIdx.x;
    if (i < N0) A[(size_t)i * N0 + i] += 1.0f;
}

// ---------------- degree / normalization ----------------
__global__ void k_colsum(const float* __restrict__ A, int n, float* __restrict__ dpart) {
    int c = blockIdx.x * blockDim.x + threadIdx.x;
    if (c >= n) return;
    int chunk = (n + DSPLIT - 1) / DSPLIT;
    int r0 = blockIdx.y * chunk;
    int r1 = min(n, r0 + chunk);
    float s = 0.f;
    for (int r = r0; r < r1; r++) s += A[(size_t)r * n + c];
    dpart[(size_t)blockIdx.y * n + c] = s;
}

__global__ void k_degfin(const float* __restrict__ A, int n,
                         const float* __restrict__ dpart,
                         float* __restrict__ dis, float* __restrict__ slw) {
    int c = blockIdx.x * blockDim.x + threadIdx.x;
    if (c >= n) return;
    float s = 0.f;
    for (int q = 0; q < DSPLIT; q++) s += dpart[(size_t)q * n + c];
    float dg = A[(size_t)c * n + c];
    float sl = (dg == 0.f) ? 2.f : 0.f;    // add_remaining_self_loops, fill=2
    float deg = s + sl;
    slw[c] = sl;
    dis[c] = (deg > 0.f) ? rsqrtf(deg) : 0.f;
}

// ---------------- x @ W, scaled by dis ----------------
template<int CIN, int COUT>
__global__ void k_xw(const float* __restrict__ x, int n, const float* __restrict__ W,
                     const float* __restrict__ dis,
                     float* __restrict__ y, float* __restrict__ z) {
    int idx = blockIdx.x * blockDim.x + threadIdx.x;
    if (idx >= n * COUT) return;
    int r = idx / COUT, j = idx % COUT;
    float s = 0.f;
    #pragma unroll
    for (int k = 0; k < CIN; k++) s += x[(size_t)r * CIN + k] * W[k * COUT + j];
    y[idx] = s;
    z[idx] = dis[r] * s;
}

// ---------------- out_part = (A^T z) split over rows ----------------
template<int COUT>
__global__ void k_atzp(const float* __restrict__ A, int n,
                       const float* __restrict__ z, float* __restrict__ part) {
    const int RC = 8;
    __shared__ float zs[RC][COUT];
    int c = blockIdx.x * blockDim.x + threadIdx.x;
    int chunk = (n + RSPLIT - 1) / RSPLIT;
    int r0b = blockIdx.y * chunk;
    int r1  = min(n, r0b + chunk);
    float acc[COUT];
    #pragma unroll
    for (int j = 0; j < COUT; j++) acc[j] = 0.f;
    for (int r0 = r0b; r0 < r1; r0 += RC) {
        __syncthreads();
        for (int t = threadIdx.x; t < RC * COUT; t += blockDim.x) {
            int rr = t / COUT, j = t % COUT;
            int r = r0 + rr;
            zs[rr][j] = (r < r1) ? z[(size_t)r * COUT + j] : 0.f;
        }
        __syncthreads();
        int rmax = min(RC, r1 - r0);
        if (c < n) {
            for (int rr = 0; rr < rmax; rr++) {
                float a = A[(size_t)(r0 + rr) * n + c];
                #pragma unroll
                for (int j = 0; j < COUT; j++) acc[j] += a * zs[rr][j];
            }
        }
    }
    if (c < n) {
        #pragma unroll
        for (int j = 0; j < COUT; j++)
            part[((size_t)blockIdx.y * n + c) * COUT + j] = acc[j];
    }
}

template<int COUT>
__global__ void k_fin(int n, const float* __restrict__ part,
                      const float* __restrict__ y, const float* __restrict__ dis,
                      const float* __restrict__ slw, const float* __restrict__ b,
                      int doRelu, float* __restrict__ out) {
    int idx = blockIdx.x * blockDim.x + threadIdx.x;
    if (idx >= n * COUT) return;
    int c = idx / COUT, j = idx % COUT;
    float s = 0.f;
    for (int q = 0; q < RSPLIT; q++) s += part[((size_t)q * n + c) * COUT + j];
    float dc = dis[c];
    float v = dc * (s + slw[c] * dc * y[idx]) + b[j];
    if (doRelu) v = fmaxf(v, 0.f);
    out[idx] = v;
}

// ---------------- top-k pooling ----------------
__global__ void k_score(const float* __restrict__ x, int n,
                        const float* __restrict__ p, float* __restrict__ s) {
    int r = blockIdx.x * blockDim.x + threadIdx.x;
    if (r >= n) return;
    float pp = 0.f, dot = 0.f;
    #pragma unroll
    for (int k = 0; k < CH; k++) {
        float pk = p[k];
        pp += pk * pk;
        dot += x[(size_t)r * CH + k] * pk;
    }
    s[r] = tanhf(dot / sqrtf(pp));
}

// rank = #{j : s[j] > s[i]  ||  (s[j]==s[i] && j<i)}  -> matches lax.top_k order
__global__ void k_rank(const float* __restrict__ score, int n, int k,
                       int* __restrict__ perm, float* __restrict__ sval) {
    __shared__ float ss[1024];
    int i = blockIdx.x * blockDim.x + threadIdx.x;
    float si = (i < n) ? score[i] : 0.f;
    int rank = 0;
    for (int j0 = 0; j0 < n; j0 += 1024) {
        int cnt = min(1024, n - j0);
        __syncthreads();
        for (int t = threadIdx.x; t < cnt; t += blockDim.x) ss[t] = score[j0 + t];
        __syncthreads();
        if (i < n) {
            for (int jj = 0; jj < cnt; jj++) {
                float sj = ss[jj];
                int j = j0 + jj;
                rank += (sj > si) || (sj == si && j < i);
            }
        }
    }
    if (i < n && rank < k) { perm[rank] = i; sval[rank] = si; }
}

__global__ void k_gpool(const float* __restrict__ x, const int* __restrict__ perm,
                        const float* __restrict__ sval, int k, float* __restrict__ xp) {
    int idx = blockIdx.x * blockDim.x + threadIdx.x;
    if (idx >= k * CH) return;
    int r = idx / CH, j = idx % CH;
    xp[idx] = x[(size_t)perm[r] * CH + j] * sval[r];
}

// ---------------- gathers -> fp16 GEMM operands ----------------
// A operand [kpM x kd]: Aop[r][kk] = A1[perm[r], kk]   (A1 = unit diag, A off-diag)
__global__ void k_gA(const float* __restrict__ A, int n, const int* __restrict__ perm,
                     int k, int kd, __half* __restrict__ H) {
    size_t idx = (size_t)blockIdx.x * blockDim.x + threadIdx.x;
    int r = (int)(idx / kd), kk = (int)(idx % kd);
    float v = 0.f;
    if (r < k && kk < n) {
        int pr = perm[r];
        v = (kk == pr) ? 1.0f : A[(size_t)pr * n + kk];
    }
    H[idx] = __float2half(v);   // small integers: exact
}

// inverse perm: rnk[j] = r if perm[r]==j else -1
__global__ void k_rnkinit(int* __restrict__ rnk, int n) {
    int i = blockIdx.x * blockDim.x + threadIdx.x;
    if (i < n) rnk[i] = -1;
}
__global__ void k_rnkset(const int* __restrict__ perm, int k, int* __restrict__ rnk) {
    int i = blockIdx.x * blockDim.x + threadIdx.x;
    if (i < k) rnk[perm[i]] = i;
}

// B operand [kpN x kd] via 32x32 tiled transpose-gather (coalesced both sides):
// Bop[rnk[j]][kk] = A1[kk][j]
__global__ void k_gBt(const float* __restrict__ A, int n, const int* __restrict__ rnk,
                      int kd, __half* __restrict__ H) {
    __shared__ float t[32][33];
    int j0 = blockIdx.x * 32, k0 = blockIdx.y * 32;
    int tx = threadIdx.x, ty = threadIdx.y;   // 32 x 8
    #pragma unroll
    for (int i = 0; i < 32; i += 8) {
        int kk = k0 + ty + i, j = j0 + tx;
        float v = 0.f;
        if (kk < n && j < n) v = (kk == j) ? 1.0f : A[(size_t)kk * n + j];
        t[ty + i][tx] = v;
    }
    __syncthreads();
    #pragma unroll
    for (int i = 0; i < 32; i += 8) {
        int j = j0 + ty + i, kk = k0 + tx;
        if (j < n && kk < kd) {
            int r = rnk[j];
            if (r >= 0) H[(size_t)r * kd + kk] = __float2half(t[tx][ty + i]);
        }
    }
}

// zero-pad K columns [n, kd) of the B operand
__global__ void k_padB(int k, int n, int kd, __half* __restrict__ H) {
    int pad = kd - n;
    int idx = blockIdx.x * blockDim.x + threadIdx.x;
    if (idx >= k * pad) return;
    int r = idx / pad, c = n + idx % pad;
    H[(size_t)r * kd + c] = __float2half(0.f);
}

// ---------------- mma.sync fp16 GEMM: C = A @ B^T, 256x128 tile ----------------
#define BM 256
#define BN 128
#define BK 32
#define STG 4
#define LDS_H 40                                  // 32 halves padded: 80B = 5 x 16B
#define STAGE_HALVES ((BM + BN) * LDS_H)
#define SMEM_HGEMM (STG * STAGE_HALVES * 2)       // 122880 bytes

__device__ __forceinline__ uint32_t smem_u32(const void* p) {
    uint32_t a;
    asm("{ .reg .u64 t; cvta.to.shared.u64 t, %1; cvt.u32.u64 %0, t; }"
        : "=r"(a) : "l"(p));
    return a;
}
__device__ __forceinline__ void cpa16(uint32_t s, const void* g) {
    asm volatile("cp.async.cg.shared.global [%0], [%1], 16;" :: "r"(s), "l"(g));
}
#define CP_COMMIT() asm volatile("cp.async.commit_group;" ::: "memory")
#define CP_WAIT(n)  asm volatile("cp.async.wait_group %0;" :: "n"(n) : "memory")

__device__ __forceinline__ void ldm_x4(uint32_t* r, uint32_t addr) {
    asm volatile("ldmatrix.sync.aligned.m8n8.x4.shared.b16 {%0,%1,%2,%3}, [%4];"
        : "=r"(r[0]), "=r"(r[1]), "=r"(r[2]), "=r"(r[3]) : "r"(addr));
}
__device__ __forceinline__ void mma16816(float* d, const uint32_t* a,
                                         uint32_t b0, uint32_t b1) {
    asm volatile("mma.sync.aligned.m16n8k16.row.col.f32.f16.f16.f32 "
        "{%0,%1,%2,%3}, {%4,%5,%6,%7}, {%8,%9}, {%0,%1,%2,%3};"
        : "+f"(d[0]), "+f"(d[1]), "+f"(d[2]), "+f"(d[3])
        : "r"(a[0]), "r"(a[1]), "r"(a[2]), "r"(a[3]), "r"(b0), "r"(b1));
}

__global__ __launch_bounds__(256, 1) void k_hgemm(
    int mreal, int nreal, int kd,
    const __half* __restrict__ Ap, const __half* __restrict__ Bp,
    float* __restrict__ C, int ldc, int zeroDiag)
{
    extern __shared__ __half sh[];
    const int tid = threadIdx.x;
    const int wid = tid >> 5, lane = tid & 31;
    const int bm = blockIdx.y * BM, bn = blockIdx.x * BN;
    const int wm0 = (wid & 3) * 64, wn0 = (wid >> 2) * 64;   // 4x2 warps, 64x64 each
    const int nch = kd / BK;

    const __half* Ag = Ap + (size_t)bm * kd;
    const __half* Bg = Bp + (size_t)bn * kd;

    float acc[4][8][4];
    #pragma unroll
    for (int mt = 0; mt < 4; mt++)
        #pragma unroll
        for (int n8 = 0; n8 < 8; n8++)
            #pragma unroll
            for (int q = 0; q < 4; q++) acc[mt][n8][q] = 0.f;

    // stage loader: A = 256 rows x 4 chunks of 16B, B = 128 rows x 4 chunks
    auto load_stage = [&](int s, int c) {
        __half* sA = sh + s * STAGE_HALVES;
        __half* sB = sA + BM * LDS_H;
        const __half* Asrc = Ag + c * BK;
        const __half* Bsrc = Bg + c * BK;
        #pragma unroll
        for (int i = 0; i < 4; i++) {
            int id = tid + (i << 8);              // 0..1023
            int row = id >> 2, c16 = id & 3;
            cpa16(smem_u32(&sA[row * LDS_H + c16 * 8]),
                  Asrc + (size_t)row * kd + c16 * 8);
        }
        #pragma unroll
        for (int i = 0; i < 2; i++) {
            int id = tid + (i << 8);              // 0..511
            int row = id >> 2, c16 = id & 3;
            cpa16(smem_u32(&sB[row * LDS_H + c16 * 8]),
                  Bsrc + (size_t)row * kd + c16 * 8);
        }
    };

    #pragma unroll
    for (int s = 0; s < STG - 1; s++) { load_stage(s, s); CP_COMMIT(); }

    const int ar = wm0 + (lane & 15);
    const int ac = (lane >> 4) * 8;
    const int br = wn0 + (lane & 7) + ((lane >> 4) & 1) * 8;
    const int bc = ((lane >> 3) & 1) * 8;

    for (int c = 0; c < nch; c++) {
        CP_WAIT(STG - 2);
        __syncthreads();

        int cf = c + STG - 1;
        if (cf < nch) load_stage(cf & (STG - 1), cf);
        CP_COMMIT();

        int s = c & (STG - 1);
        const __half* sA = sh + s * STAGE_HALVES;
        const __half* sB = sA + BM * LDS_H;
        #pragma unroll
        for (int k16 = 0; k16 < 2; k16++) {
            uint32_t a[4][4];
            #pragma unroll
            for (int mt = 0; mt < 4; mt++)
                ldm_x4(a[mt], smem_u32(&sA[(ar + mt * 16) * LDS_H + k16 * 16 + ac]));
            uint32_t b[4][4];
            #pragma unroll
            for (int ng = 0; ng < 4; ng++)
                ldm_x4(b[ng], smem_u32(&sB[(br + ng * 16) * LDS_H + k16 * 16 + bc]));
            #pragma unroll
            for (int mt = 0; mt < 4; mt++)
                #pragma unroll
                for (int n8 = 0; n8 < 8; n8++) {
                    int ng = n8 >> 1, hi = (n8 & 1) << 1;
                    mma16816(acc[mt][n8], a[mt], b[ng][hi], b[ng][hi + 1]);
                }
        }
        __syncthreads();
    }

    // epilogue: direct coalesced stores
    int g = lane >> 2, tg = lane & 3;
    #pragma unroll
    for (int mt = 0; mt < 4; mt++) {
        #pragma unroll
        for (int n8 = 0; n8 < 8; n8++) {
            int r1 = bm + wm0 + mt * 16 + g;
            int r2 = r1 + 8;
            int c0 = bn + wn0 + n8 * 8 + tg * 2;
            float* a4 = acc[mt][n8];
            if (r1 < mreal) {
                if (c0 < nreal)
                    C[(size_t)r1 * ldc + c0] = (zeroDiag && r1 == c0) ? 0.f : a4[0];
                if (c0 + 1 < nreal)
                    C[(size_t)r1 * ldc + c0 + 1] = (zeroDiag && r1 == c0 + 1) ? 0.f : a4[1];
            }
            if (r2 < mreal) {
                if (c0 < nreal)
                    C[(size_t)r2 * ldc + c0] = (zeroDiag && r2 == c0) ? 0.f : a4[2];
                if (c0 + 1 < nreal)
                    C[(size_t)r2 * ldc + c0 + 1] = (zeroDiag && r2 == c0 + 1) ? 0.f : a4[3];
            }
        }
    }
}

// ---------------- unpool: res[perm[r]] += xup[r] ----------------
__global__ void k_unpool(float* __restrict__ res, const float* __restrict__ xup,
                         const int* __restrict__ perm, int k) {
    int idx = blockIdx.x * blockDim.x + threadIdx.x;
    if (idx >= k * CH) return;
    int r = idx / CH, j = idx % CH;
    res[(size_t)perm[r] * CH + j] += xup[idx];
}

// ---------------- host orchestration ----------------
struct DevPtrs {
    float *A0, *A1, *A2, *A3;
    __half *Ah, *Bh;
    float *x0, *x1, *x2, *x3, *xp, *y, *z, *part, *dpart, *dis, *slw, *score, *sval;
    int *perm0, *perm1, *perm2, *rnk;
};
static DevPtrs P;
static bool g_init = false;

template<int CIN, int COUT>
static void gcn(const float* A, int n, const float* xin, const float* W,
                const float* b, bool relu, float* out) {
    dim3 cs(cdiv(n, 256), DSPLIT);
    k_colsum<<<cs, 256>>>(A, n, P.dpart);
    k_degfin<<<cdiv(n, 256), 256>>>(A, n, P.dpart, P.dis, P.slw);
    k_xw<CIN, COUT><<<cdiv(n * COUT, 256), 256>>>(xin, n, W, P.dis, P.y, P.z);
    dim3 ag(cdiv(n, 256), RSPLIT);
    k_atzp<COUT><<<ag, 256>>>(A, n, P.z, P.part);
    k_fin<COUT><<<cdiv(n * COUT, 256), 256>>>(n, P.part, P.y, P.dis, P.slw, b,
                                              relu ? 1 : 0, out);
}

static void pool_level(const float* A, int n, int k, int kpN, int kpM, int kd,
                       const float* x, const float* p, int* perm, float* Anext) {
    k_score<<<cdiv(n, 256), 256>>>(x, n, p, P.score);
    k_rank<<<cdiv(n, 256), 256>>>(P.score, n, k, perm, P.sval);
    k_gpool<<<cdiv(k * CH, 256), 256>>>(x, perm, P.sval, k, P.xp);
    // A operand: row gather (coalesced)
    size_t tot = (size_t)kpM * kd;
    k_gA<<<(int)((tot + 255) / 256), 256>>>(A, n, perm, k, kd, P.Ah);
    // B operand: tiled transpose-gather (coalesced)
    k_rnkinit<<<cdiv(n, 256), 256>>>(P.rnk, n);
    k_rnkset<<<cdiv(k, 256), 256>>>(perm, k, P.rnk);
    dim3 tg(cdiv(n, 32), cdiv(n, 32));
    k_gBt<<<tg, dim3(32, 8)>>>(A, n, P.rnk, kd, P.Bh);
    if (kd > n) {
        int pad = kd - n;
        k_padB<<<cdiv(k * pad, 256), 256>>>(k, n, kd, P.Bh);
    }
    dim3 gg(kpN / 128, kpM / 256);
    k_hgemm<<<gg, 256, SMEM_HGEMM>>>(k, k, kd, P.Ah, P.Bh, Anext, k, 1);
}

extern "C" void kernel_launch(void* const* d_in, const int* in_sizes, int n_in,
                              void* d_out, int out_size) {
    if (!g_init) {
        cudaGetSymbolAddress((void**)&P.A0, g_A0);
        cudaGetSymbolAddress((void**)&P.A1, g_A1);
        cudaGetSymbolAddress((void**)&P.A2, g_A2);
        cudaGetSymbolAddress((void**)&P.A3, g_A3);
        cudaGetSymbolAddress((void**)&P.Ah, g_Ah);
        cudaGetSymbolAddress((void**)&P.Bh, g_Bh);
        cudaGetSymbolAddress((void**)&P.x0, g_x0);
        cudaGetSymbolAddress((void**)&P.x1, g_x1);
        cudaGetSymbolAddress((void**)&P.x2, g_x2);
        cudaGetSymbolAddress((void**)&P.x3, g_x3);
        cudaGetSymbolAddress((void**)&P.xp, g_xp);
        cudaGetSymbolAddress((void**)&P.y,  g_y);
        cudaGetSymbolAddress((void**)&P.z,  g_z);
        cudaGetSymbolAddress((void**)&P.part,  g_part);
        cudaGetSymbolAddress((void**)&P.dpart, g_dpart);
        cudaGetSymbolAddress((void**)&P.dis,   g_dis);
        cudaGetSymbolAddress((void**)&P.slw,   g_slw);
        cudaGetSymbolAddress((void**)&P.score, g_score);
        cudaGetSymbolAddress((void**)&P.sval,  g_sval);
        cudaGetSymbolAddress((void**)&P.perm0, g_perm0);
        cudaGetSymbolAddress((void**)&P.perm1, g_perm1);
        cudaGetSymbolAddress((void**)&P.perm2, g_perm2);
        cudaGetSymbolAddress((void**)&P.rnk,   g_rnk);
        cudaFuncSetAttribute(k_hgemm, cudaFuncAttributeMaxDynamicSharedMemorySize,
                             SMEM_HGEMM);
        g_init = true;
    }

    const float* x_in = (const float*)d_in[0];
    const int*   ei   = (const int*)d_in[1];
    const float* W0 = (const float*)d_in[2];  const float* b0 = (const float*)d_in[3];
    const float* W1 = (const float*)d_in[4];  const float* b1 = (const float*)d_in[5];
    const float* W2 = (const float*)d_in[6];  const float* b2 = (const float*)d_in[7];
    const float* W3 = (const float*)d_in[8];  const float* b3 = (const float*)d_in[9];
    const float* p1 = (const float*)d_in[10];
    const float* p2 = (const float*)d_in[11];
    const float* p3 = (const float*)d_in[12];
    const float* U0 = (const float*)d_in[13]; const float* c0 = (const float*)d_in[14];
    const float* U1 = (const float*)d_in[15]; const float* c1 = (const float*)d_in[16];
    const float* U2 = (const float*)d_in[17]; const float* c2 = (const float*)d_in[18];
    float* out = (float*)d_out;

    // A0 = dense adjacency with parallel-edge accumulation + unit self loops
    k_zero<<<cdiv(N0 * N0, 256), 256>>>(P.A0, N0 * N0);
    k_edges<<<cdiv(EDG, 256), 256>>>(ei, ei + EDG, P.A0);
    k_diag1<<<cdiv(N0, 256), 256>>>(P.A0);

    // ---- down path ----
    gcn<20, 64>(P.A0, N0, x_in, W0, b0, true, P.x0);

    pool_level(P.A0, N0, K1, KP1, KPM1, KD1, P.x0, p1, P.perm0, P.A1);
    gcn<64, 64>(P.A1, K1, P.xp, W1, b1, true, P.x1);

    pool_level(P.A1, K1, K2, KP2, KPM2, KD2, P.x1, p2, P.perm1, P.A2);
    gcn<64, 64>(P.A2, K2, P.xp, W2, b2, true, P.x2);

    pool_level(P.A2, K2, K3, KP3, KPM3, KD3, P.x2, p3, P.perm2, P.A3);
    gcn<64, 64>(P.A3, K3, P.xp, W3, b3, true, P.x3);

    // ---- up path ----
    k_unpool<<<cdiv(K3 * CH, 256), 256>>>(P.x2, P.x3, P.perm2, K3);
    gcn<64, 64>(P.A2, K2, P.x2, U0, c0, true, P.xp);

    k_unpool<<<cdiv(K2 * CH, 256), 256>>>(P.x1, P.xp, P.perm1, K2);
    gcn<64, 64>(P.A1, K1, P.x1, U1, c1, true, P.xp);

    k_unpool<<<cdiv(K1 * CH, 256), 256>>>(P.x0, P.xp, P.perm0, K1);
    gcn<64, 20>(P.A0, N0, P.x0, U2, c2, false, out);
}

// round 9
// speedup vs baseline: 1.1710x; 1.1710x over previous
#include <cuda_runtime.h>
#include <cuda_fp16.h>
#include <math.h>
#include <stdint.h>

// ---------------- problem constants ----------------
#define N0   4096
#define EDG  131072
#define K1   3277      // ceil(0.8*4096)
#define K2   2622      // ceil(0.8*3277)
#define K3   2098      // ceil(0.8*2622)
#define KP1  3328      // K1 padded to 128 (GEMM M/N tiles)
#define KP2  2688
#define KP3  2176
#define KD1  4096      // GEMM K dim padded to 64
#define KD2  3328
#define KD3  2624
#define CH   64
#define DSPLIT 32
#define RSPLIT 16

// ---------------- device scratch (no allocation allowed) ----------------
__device__ float g_A0[(size_t)N0*N0];
__device__ float g_A1[(size_t)K1*K1];
__device__ float g_A2[(size_t)K2*K2];
__device__ float g_A3[(size_t)K3*K3];
__device__ __half g_Ah[(size_t)KP1*KD1];   // GEMM operand A, [M,K] row-major
__device__ __half g_Bh[(size_t)KP1*KD1];   // GEMM operand B, [N,K] row-major
__device__ float g_x0[N0*CH];
__device__ float g_x1[K1*CH];
__device__ float g_x2[K2*CH];
__device__ float g_x3[K3*CH];
__device__ float g_xp[N0*CH];
__device__ float g_y [N0*CH];
__device__ float g_z [N0*CH];
__device__ float g_part [(size_t)RSPLIT*N0*CH];
__device__ float g_dpart[(size_t)DSPLIT*N0];
__device__ float g_dis[N0];
__device__ float g_slw[N0];
__device__ float g_score[N0];
__device__ float g_sval[N0];
__device__ int   g_perm0[K1];
__device__ int   g_perm1[K2];
__device__ int   g_perm2[K3];
__device__ int   g_rnk[N0];

static inline int cdiv(int a, int b) { return (a + b - 1) / b; }

// ---------------- elementwise ----------------
__global__ void k_zero(float* p, int n) {
    int i = blockIdx.x * blockDim.x + threadIdx.x;
    if (i < n) p[i] = 0.f;
}

__global__ void k_edges(const int* __restrict__ src, const int* __restrict__ dst,
                        float* __restrict__ A) {
    int i = blockIdx.x * blockDim.x + threadIdx.x;
    if (i >= EDG) return;
    int s = src[i], d = dst[i];
    if (s != d) atomicAdd(&A[(size_t)s * N0 + d], 1.0f);   // exact integer adds
}

__global__ void k_diag1(float* A) {
    int i = blockIdx.x * blockDim.x + threadIdx.x;
    if (i < N0) A[(size_t)i * N0 + i] += 1.0f;
}

// ---------------- degree / normalization ----------------
__global__ void k_colsum(const float* __restrict__ A, int n, float* __restrict__ dpart) {
    int c = blockIdx.x * blockDim.x + threadIdx.x;
    if (c >= n) return;
    int chunk = (n + DSPLIT - 1) / DSPLIT;
    int r0 = blockIdx.y * chunk;
    int r1 = min(n, r0 + chunk);
    float s = 0.f;
    for (int r = r0; r < r1; r++) s += A[(size_t)r * n + c];
    dpart[(size_t)blockIdx.y * n + c] = s;
}

__global__ void k_degfin(const float* __restrict__ A, int n,
                         const float* __restrict__ dpart,
                         float* __restrict__ dis, float* __restrict__ slw) {
    int c = blockIdx.x * blockDim.x + threadIdx.x;
    if (c >= n) return;
    float s = 0.f;
    for (int q = 0; q < DSPLIT; q++) s += dpart[(size_t)q * n + c];
    float dg = A[(size_t)c * n + c];
    float sl = (dg == 0.f) ? 2.f : 0.f;    // add_remaining_self_loops, fill=2
    float deg = s + sl;
    slw[c] = sl;
    dis[c] = (deg > 0.f) ? rsqrtf(deg) : 0.f;
}

// ---------------- x @ W, scaled by dis ----------------
template<int CIN, int COUT>
__global__ void k_xw(const float* __restrict__ x, int n, const float* __restrict__ W,
                     const float* __restrict__ dis,
                     float* __restrict__ y, float* __restrict__ z) {
    int idx = blockIdx.x * blockDim.x + threadIdx.x;
    if (idx >= n * COUT) return;
    int r = idx / COUT, j = idx % COUT;
    float s = 0.f;
    #pragma unroll
    for (int k = 0; k < CIN; k++) s += x[(size_t)r * CIN + k] * W[k * COUT + j];
    y[idx] = s;
    z[idx] = dis[r] * s;
}

// ---------------- out_part = (A^T z) split over rows ----------------
template<int COUT>
__global__ void k_atzp(const float* __restrict__ A, int n,
                       const float* __restrict__ z, float* __restrict__ part) {
    const int RC = 8;
    __shared__ float zs[RC][COUT];
    int c = blockIdx.x * blockDim.x + threadIdx.x;
    int chunk = (n + RSPLIT - 1) / RSPLIT;
    int r0b = blockIdx.y * chunk;
    int r1  = min(n, r0b + chunk);
    float acc[COUT];
    #pragma unroll
    for (int j = 0; j < COUT; j++) acc[j] = 0.f;
    for (int r0 = r0b; r0 < r1; r0 += RC) {
        __syncthreads();
        for (int t = threadIdx.x; t < RC * COUT; t += blockDim.x) {
            int rr = t / COUT, j = t % COUT;
            int r = r0 + rr;
            zs[rr][j] = (r < r1) ? z[(size_t)r * COUT + j] : 0.f;
        }
        __syncthreads();
        int rmax = min(RC, r1 - r0);
        if (c < n) {
            for (int rr = 0; rr < rmax; rr++) {
                float a = A[(size_t)(r0 + rr) * n + c];
                #pragma unroll
                for (int j = 0; j < COUT; j++) acc[j] += a * zs[rr][j];
            }
        }
    }
    if (c < n) {
        #pragma unroll
        for (int j = 0; j < COUT; j++)
            part[((size_t)blockIdx.y * n + c) * COUT + j] = acc[j];
    }
}

template<int COUT>
__global__ void k_fin(int n, const float* __restrict__ part,
                      const float* __restrict__ y, const float* __restrict__ dis,
                      const float* __restrict__ slw, const float* __restrict__ b,
                      int doRelu, float* __restrict__ out) {
    int idx = blockIdx.x * blockDim.x + threadIdx.x;
    if (idx >= n * COUT) return;
    int c = idx / COUT, j = idx % COUT;
    float s = 0.f;
    for (int q = 0; q < RSPLIT; q++) s += part[((size_t)q * n + c) * COUT + j];
    float dc = dis[c];
    float v = dc * (s + slw[c] * dc * y[idx]) + b[j];
    if (doRelu) v = fmaxf(v, 0.f);
    out[idx] = v;
}

// ---------------- top-k pooling ----------------
__global__ void k_score(const float* __restrict__ x, int n,
                        const float* __restrict__ p, float* __restrict__ s) {
    int r = blockIdx.x * blockDim.x + threadIdx.x;
    if (r >= n) return;
    float pp = 0.f, dot = 0.f;
    #pragma unroll
    for (int k = 0; k < CH; k++) {
        float pk = p[k];
        pp += pk * pk;
        dot += x[(size_t)r * CH + k] * pk;
    }
    s[r] = tanhf(dot / sqrtf(pp));
}

// rank = #{j : s[j] > s[i]  ||  (s[j]==s[i] && j<i)}  -> matches lax.top_k order
__global__ void k_rank(const float* __restrict__ score, int n, int k,
                       int* __restrict__ perm, float* __restrict__ sval) {
    __shared__ float ss[1024];
    int i = blockIdx.x * blockDim.x + threadIdx.x;
    float si = (i < n) ? score[i] : 0.f;
    int rank = 0;
    for (int j0 = 0; j0 < n; j0 += 1024) {
        int cnt = min(1024, n - j0);
        __syncthreads();
        for (int t = threadIdx.x; t < cnt; t += blockDim.x) ss[t] = score[j0 + t];
        __syncthreads();
        if (i < n) {
            for (int jj = 0; jj < cnt; jj++) {
                float sj = ss[jj];
                int j = j0 + jj;
                rank += (sj > si) || (sj == si && j < i);
            }
        }
    }
    if (i < n && rank < k) { perm[rank] = i; sval[rank] = si; }
}

__global__ void k_gpool(const float* __restrict__ x, const int* __restrict__ perm,
                        const float* __restrict__ sval, int k, float* __restrict__ xp) {
    int idx = blockIdx.x * blockDim.x + threadIdx.x;
    if (idx >= k * CH) return;
    int r = idx / CH, j = idx % CH;
    xp[idx] = x[(size_t)perm[r] * CH + j] * sval[r];
}

// ---------------- gathers -> fp16 GEMM operands ----------------
// A operand [kp x kd]: Aop[r][kk] = A1[perm[r], kk]   (A1 = unit diag, A off-diag)
__global__ void k_gA(const float* __restrict__ A, int n, const int* __restrict__ perm,
                     int k, int kd, __half* __restrict__ H) {
    size_t idx = (size_t)blockIdx.x * blockDim.x + threadIdx.x;
    int r = (int)(idx / kd), kk = (int)(idx % kd);
    float v = 0.f;
    if (r < k && kk < n) {
        int pr = perm[r];
        v = (kk == pr) ? 1.0f : A[(size_t)pr * n + kk];
    }
    H[idx] = __float2half(v);   // small integers: exact
}

// inverse perm: rnk[j] = r if perm[r]==j else -1
__global__ void k_rnkinit(int* __restrict__ rnk, int n) {
    int i = blockIdx.x * blockDim.x + threadIdx.x;
    if (i < n) rnk[i] = -1;
}
__global__ void k_rnkset(const int* __restrict__ perm, int k, int* __restrict__ rnk) {
    int i = blockIdx.x * blockDim.x + threadIdx.x;
    if (i < k) rnk[perm[i]] = i;
}

// B operand [kpN x kd] via 32x32 tiled transpose-gather (coalesced both sides):
// Bop[rnk[j]][kk] = A1[kk][j]
__global__ void k_gBt(const float* __restrict__ A, int n, const int* __restrict__ rnk,
                      int kd, __half* __restrict__ H) {
    __shared__ float t[32][33];
    int j0 = blockIdx.x * 32, k0 = blockIdx.y * 32;
    int tx = threadIdx.x, ty = threadIdx.y;   // 32 x 8
    #pragma unroll
    for (int i = 0; i < 32; i += 8) {
        int kk = k0 + ty + i, j = j0 + tx;
        float v = 0.f;
        if (kk < n && j < n) v = (kk == j) ? 1.0f : A[(size_t)kk * n + j];
        t[ty + i][tx] = v;
    }
    __syncthreads();
    #pragma unroll
    for (int i = 0; i < 32; i += 8) {
        int j = j0 + ty + i, kk = k0 + tx;
        if (j < n && kk < kd) {
            int r = rnk[j];
            if (r >= 0) H[(size_t)r * kd + kk] = __float2half(t[tx][ty + i]);
        }
    }
}

// zero-pad K columns [n, kd) of the B operand
__global__ void k_padB(int k, int n, int kd, __half* __restrict__ H) {
    int pad = kd - n;
    int idx = blockIdx.x * blockDim.x + threadIdx.x;
    if (idx >= k * pad) return;
    int r = idx / pad, c = n + idx % pad;
    H[(size_t)r * kd + c] = __float2half(0.f);
}

// ---------------- mma.sync fp16 GEMM: C = A @ B^T, 128x128 tile ----------------
#define BM 128
#define BN 128
#define BK 64
#define STG 3
#define LDS_H 72                      // padded halves/row: 144B = 9 x 16B
#define STAGE_HALVES (2 * 128 * LDS_H)
#define SMEM_HGEMM (STG * STAGE_HALVES * 2)   // 110592 bytes -> 2 CTAs/SM

__device__ __forceinline__ uint32_t smem_u32(const void* p) {
    uint32_t a;
    asm("{ .reg .u64 t; cvta.to.shared.u64 t, %1; cvt.u32.u64 %0, t; }"
        : "=r"(a) : "l"(p));
    return a;
}
__device__ __forceinline__ void cpa16(uint32_t s, const void* g) {
    asm volatile("cp.async.cg.shared.global [%0], [%1], 16;" :: "r"(s), "l"(g));
}
#define CP_COMMIT() asm volatile("cp.async.commit_group;" ::: "memory")
#define CP_WAIT(n)  asm volatile("cp.async.wait_group %0;" :: "n"(n) : "memory")

__device__ __forceinline__ void ldm_x4(uint32_t* r, uint32_t addr) {
    asm volatile("ldmatrix.sync.aligned.m8n8.x4.shared.b16 {%0,%1,%2,%3}, [%4];"
        : "=r"(r[0]), "=r"(r[1]), "=r"(r[2]), "=r"(r[3]) : "r"(addr));
}
__device__ __forceinline__ void mma16816(float* d, const uint32_t* a,
                                         uint32_t b0, uint32_t b1) {
    asm volatile("mma.sync.aligned.m16n8k16.row.col.f32.f16.f16.f32 "
        "{%0,%1,%2,%3}, {%4,%5,%6,%7}, {%8,%9}, {%0,%1,%2,%3};"
        : "+f"(d[0]), "+f"(d[1]), "+f"(d[2]), "+f"(d[3])
        : "r"(a[0]), "r"(a[1]), "r"(a[2]), "r"(a[3]), "r"(b0), "r"(b1));
}

__global__ __launch_bounds__(256, 2) void k_hgemm(
    int mreal, int nreal, int kd,
    const __half* __restrict__ Ap, const __half* __restrict__ Bp,
    float* __restrict__ C, int ldc, int zeroDiag)
{
    extern __shared__ __half sh[];
    const int tid = threadIdx.x;
    const int wid = tid >> 5, lane = tid & 31;
    const int bm = blockIdx.y * BM, bn = blockIdx.x * BN;
    const int wm0 = (wid & 3) * 32, wn0 = (wid >> 2) * 64;
    const int nch = kd / BK;

    const __half* Ag = Ap + (size_t)bm * kd;
    const __half* Bg = Bp + (size_t)bn * kd;

    const int lc8 = tid & 7;          // 16B column within 64-half chunk
    const int lr0 = tid >> 3;         // base row

    float acc[2][8][4];
    #pragma unroll
    for (int mt = 0; mt < 2; mt++)
        #pragma unroll
        for (int n8 = 0; n8 < 8; n8++)
            #pragma unroll
            for (int q = 0; q < 4; q++) acc[mt][n8][q] = 0.f;

    // prologue: stages 0..STG-2
    #pragma unroll
    for (int s = 0; s < STG - 1; s++) {
        __half* sA = sh + s * STAGE_HALVES;
        __half* sB = sA + 128 * LDS_H;
        const __half* Asrc = Ag + s * BK;
        const __half* Bsrc = Bg + s * BK;
        #pragma unroll
        for (int i = 0; i < 4; i++) {
            int row = lr0 + i * 32;
            cpa16(smem_u32(&sA[row * LDS_H + lc8 * 8]), Asrc + (size_t)row * kd + lc8 * 8);
            cpa16(smem_u32(&sB[row * LDS_H + lc8 * 8]), Bsrc + (size_t)row * kd + lc8 * 8);
        }
        CP_COMMIT();
    }

    for (int c = 0; c < nch; c++) {
        CP_WAIT(STG - 2);
        __syncthreads();

        // prefetch chunk c+STG-1
        {
            int cf = c + STG - 1;
            if (cf < nch) {
                int s = cf % STG;
                __half* sA = sh + s * STAGE_HALVES;
                __half* sB = sA + 128 * LDS_H;
                const __half* Asrc = Ag + cf * BK;
                const __half* Bsrc = Bg + cf * BK;
                #pragma unroll
                for (int i = 0; i < 4; i++) {
                    int row = lr0 + i * 32;
                    cpa16(smem_u32(&sA[row * LDS_H + lc8 * 8]),
                          Asrc + (size_t)row * kd + lc8 * 8);
                    cpa16(smem_u32(&sB[row * LDS_H + lc8 * 8]),
                          Bsrc + (size_t)row * kd + lc8 * 8);
                }
            }
            CP_COMMIT();
        }

        // compute on stage c % STG
        {
            int s = c % STG;
            const __half* sA = sh + s * STAGE_HALVES;
            const __half* sB = sA + 128 * LDS_H;
            int ar = wm0 + (lane & 15);
            int ac = (lane >> 4) * 8;
            int br = wn0 + (lane & 7) + ((lane >> 4) & 1) * 8;
            int bc = ((lane >> 3) & 1) * 8;
            #pragma unroll
            for (int k16 = 0; k16 < 4; k16++) {
                uint32_t a[2][4];
                #pragma unroll
                for (int mt = 0; mt < 2; mt++)
                    ldm_x4(a[mt], smem_u32(&sA[(ar + mt * 16) * LDS_H + k16 * 16 + ac]));
                uint32_t b[4][4];
                #pragma unroll
                for (int ng = 0; ng < 4; ng++)
                    ldm_x4(b[ng], smem_u32(&sB[(br + ng * 16) * LDS_H + k16 * 16 + bc]));
                #pragma unroll
                for (int mt = 0; mt < 2; mt++)
                    #pragma unroll
                    for (int n8 = 0; n8 < 8; n8++) {
                        int ng = n8 >> 1, hi = (n8 & 1) << 1;
                        mma16816(acc[mt][n8], a[mt], b[ng][hi], b[ng][hi + 1]);
                    }
            }
        }
        __syncthreads();
    }

    // epilogue: direct coalesced stores (8x8 patches -> 8 full 32B sectors)
    int g = lane >> 2, tg = lane & 3;
    #pragma unroll
    for (int mt = 0; mt < 2; mt++) {
        #pragma unroll
        for (int n8 = 0; n8 < 8; n8++) {
            int r1 = bm + wm0 + mt * 16 + g;
            int r2 = r1 + 8;
            int c0 = bn + wn0 + n8 * 8 + tg * 2;
            float* a4 = acc[mt][n8];
            if (r1 < mreal) {
                if (c0 < nreal)
                    C[(size_t)r1 * ldc + c0] = (zeroDiag && r1 == c0) ? 0.f : a4[0];
                if (c0 + 1 < nreal)
                    C[(size_t)r1 * ldc + c0 + 1] = (zeroDiag && r1 == c0 + 1) ? 0.f : a4[1];
            }
            if (r2 < mreal) {
                if (c0 < nreal)
                    C[(size_t)r2 * ldc + c0] = (zeroDiag && r2 == c0) ? 0.f : a4[2];
                if (c0 + 1 < nreal)
                    C[(size_t)r2 * ldc + c0 + 1] = (zeroDiag && r2 == c0 + 1) ? 0.f : a4[3];
            }
        }
    }
}

// ---------------- unpool: res[perm[r]] += xup[r] ----------------
__global__ void k_unpool(float* __restrict__ res, const float* __restrict__ xup,
                         const int* __restrict__ perm, int k) {
    int idx = blockIdx.x * blockDim.x + threadIdx.x;
    if (idx >= k * CH) return;
    int r = idx / CH, j = idx % CH;
    res[(size_t)perm[r] * CH + j] += xup[idx];
}

// ---------------- host orchestration ----------------
struct DevPtrs {
    float *A0, *A1, *A2, *A3;
    __half *Ah, *Bh;
    float *x0, *x1, *x2, *x3, *xp, *y, *z, *part, *dpart, *dis, *slw, *score, *sval;
    int *perm0, *perm1, *perm2, *rnk;
};
static DevPtrs P;
static bool g_init = false;

template<int CIN, int COUT>
static void gcn(const float* A, int n, const float* xin, const float* W,
                const float* b, bool relu, float* out) {
    dim3 cs(cdiv(n, 256), DSPLIT);
    k_colsum<<<cs, 256>>>(A, n, P.dpart);
    k_degfin<<<cdiv(n, 256), 256>>>(A, n, P.dpart, P.dis, P.slw);
    k_xw<CIN, COUT><<<cdiv(n * COUT, 256), 256>>>(xin, n, W, P.dis, P.y, P.z);
    dim3 ag(cdiv(n, 256), RSPLIT);
    k_atzp<COUT><<<ag, 256>>>(A, n, P.z, P.part);
    k_fin<COUT><<<cdiv(n * COUT, 256), 256>>>(n, P.part, P.y, P.dis, P.slw, b,
                                              relu ? 1 : 0, out);
}

static void pool_level(const float* A, int n, int k, int kp, int kd,
                       const float* x, const float* p, int* perm, float* Anext) {
    k_score<<<cdiv(n, 256), 256>>>(x, n, p, P.score);
    k_rank<<<cdiv(n, 256), 256>>>(P.score, n, k, perm, P.sval);
    k_gpool<<<cdiv(k * CH, 256), 256>>>(x, perm, P.sval, k, P.xp);
    // A operand: row gather (coalesced)
    size_t tot = (size_t)kp * kd;
    k_gA<<<(int)((tot + 255) / 256), 256>>>(A, n, perm, k, kd, P.Ah);
    // B operand: tiled transpose-gather (coalesced)
    k_rnkinit<<<cdiv(n, 256), 256>>>(P.rnk, n);
    k_rnkset<<<cdiv(k, 256), 256>>>(perm, k, P.rnk);
    dim3 tg(cdiv(n, 32), cdiv(n, 32));
    k_gBt<<<tg, dim3(32, 8)>>>(A, n, P.rnk, kd, P.Bh);
    if (kd > n) {
        int pad = kd - n;
        k_padB<<<cdiv(k * pad, 256), 256>>>(k, n, kd, P.Bh);
    }
    dim3 gg(kp / 128, kp / 128);
    k_hgemm<<<gg, 256, SMEM_HGEMM>>>(k, k, kd, P.Ah, P.Bh, Anext, k, 1);
}

extern "C" void kernel_launch(void* const* d_in, const int* in_sizes, int n_in,
                              void* d_out, int out_size) {
    if (!g_init) {
        cudaGetSymbolAddress((void**)&P.A0, g_A0);
        cudaGetSymbolAddress((void**)&P.A1, g_A1);
        cudaGetSymbolAddress((void**)&P.A2, g_A2);
        cudaGetSymbolAddress((void**)&P.A3, g_A3);
        cudaGetSymbolAddress((void**)&P.Ah, g_Ah);
        cudaGetSymbolAddress((void**)&P.Bh, g_Bh);
        cudaGetSymbolAddress((void**)&P.x0, g_x0);
        cudaGetSymbolAddress((void**)&P.x1, g_x1);
        cudaGetSymbolAddress((void**)&P.x2, g_x2);
        cudaGetSymbolAddress((void**)&P.x3, g_x3);
        cudaGetSymbolAddress((void**)&P.xp, g_xp);
        cudaGetSymbolAddress((void**)&P.y,  g_y);
        cudaGetSymbolAddress((void**)&P.z,  g_z);
        cudaGetSymbolAddress((void**)&P.part,  g_part);
        cudaGetSymbolAddress((void**)&P.dpart, g_dpart);
        cudaGetSymbolAddress((void**)&P.dis,   g_dis);
        cudaGetSymbolAddress((void**)&P.slw,   g_slw);
        cudaGetSymbolAddress((void**)&P.score, g_score);
        cudaGetSymbolAddress((void**)&P.sval,  g_sval);
        cudaGetSymbolAddress((void**)&P.perm0, g_perm0);
        cudaGetSymbolAddress((void**)&P.perm1, g_perm1);
        cudaGetSymbolAddress((void**)&P.perm2, g_perm2);
        cudaGetSymbolAddress((void**)&P.rnk,   g_rnk);
        cudaFuncSetAttribute(k_hgemm, cudaFuncAttributeMaxDynamicSharedMemorySize,
                             SMEM_HGEMM);
        g_init = true;
    }

    const float* x_in = (const float*)d_in[0];
    const int*   ei   = (const int*)d_in[1];
    const float* W0 = (const float*)d_in[2];  const float* b0 = (const float*)d_in[3];
    const float* W1 = (const float*)d_in[4];  const float* b1 = (const float*)d_in[5];
    const float* W2 = (const float*)d_in[6];  const float* b2 = (const float*)d_in[7];
    const float* W3 = (const float*)d_in[8];  const float* b3 = (const float*)d_in[9];
    const float* p1 = (const float*)d_in[10];
    const float* p2 = (const float*)d_in[11];
    const float* p3 = (const float*)d_in[12];
    const float* U0 = (const float*)d_in[13]; const float* c0 = (const float*)d_in[14];
    const float* U1 = (const float*)d_in[15]; const float* c1 = (const float*)d_in[16];
    const float* U2 = (const float*)d_in[17]; const float* c2 = (const float*)d_in[18];
    float* out = (float*)d_out;

    // A0 = dense adjacency with parallel-edge accumulation + unit self loops
    k_zero<<<cdiv(N0 * N0, 256), 256>>>(P.A0, N0 * N0);
    k_edges<<<cdiv(EDG, 256), 256>>>(ei, ei + EDG, P.A0);
    k_diag1<<<cdiv(N0, 256), 256>>>(P.A0);

    // ---- down path ----
    gcn<20, 64>(P.A0, N0, x_in, W0, b0, true, P.x0);

    pool_level(P.A0, N0, K1, KP1, KD1, P.x0, p1, P.perm0, P.A1);
    gcn<64, 64>(P.A1, K1, P.xp, W1, b1, true, P.x1);

    pool_level(P.A1, K1, K2, KP2, KD2, P.x1, p2, P.perm1, P.A2);
    gcn<64, 64>(P.A2, K2, P.xp, W2, b2, true, P.x2);

    pool_level(P.A2, K2, K3, KP3, KD3, P.x2, p3, P.perm2, P.A3);
    gcn<64, 64>(P.A3, K3, P.xp, W3, b3, true, P.x3);

    // ---- up path ----
    k_unpool<<<cdiv(K3 * CH, 256), 256>>>(P.x2, P.x3, P.perm2, K3);
    gcn<64, 64>(P.A2, K2, P.x2, U0, c0, true, P.xp);

    k_unpool<<<cdiv(K2 * CH, 256), 256>>>(P.x1, P.xp, P.perm1, K2);
    gcn<64, 64>(P.A1, K1, P.x1, U1, c1, true, P.xp);

    k_unpool<<<cdiv(K1 * CH, 256), 256>>>(P.x0, P.xp, P.perm0, K1);
    gcn<64, 20>(P.A0, N0, P.x0, U2, c2, false, out);
}